// round 1
// baseline (speedup 1.0000x reference)
#include <cuda_runtime.h>

// ChunkedValueCrossAttn: softmax over a single context token == 1.0, so the
// output is y[b,c,h,w] = (Wo @ (Wv @ context[b]))[c] + bo[c], a constant per
// (b,c) broadcast over HxW. x/Wq/Wk are dead inputs.
//
// Shapes (fixed by the problem):
//   B=2, C(query_dim)=64, H=W=1024, inner=32, context_dim=16
//   out: [2, 64, 1024, 1024] f32 = 134,217,728 elements

#define B_       2
#define CQ_      64
#define INNER_   32
#define CTX_     16
#define HW_      (1024 * 1024)          // floats per (b,c) slab
#define HW4_     (HW_ / 4)              // float4 per slab = 262144 = 1<<18
#define NCONST_  (B_ * CQ_)             // 128

__device__ float g_const[NCONST_];

// One block, 128 threads: compute the 128 broadcast constants.
__global__ void compute_consts_kernel(const float* __restrict__ context,
                                      const float* __restrict__ Wv,
                                      const float* __restrict__ Wo,
                                      const float* __restrict__ bo) {
    __shared__ float s_v[B_][INNER_];   // v = context @ Wv^T  -> [B, inner]
    int tid = threadIdx.x;

    if (tid < B_ * INNER_) {
        int b = tid / INNER_;
        int o = tid % INNER_;
        float acc = 0.f;
        #pragma unroll
        for (int j = 0; j < CTX_; ++j)
            acc += Wv[o * CTX_ + j] * context[b * CTX_ + j];
        s_v[b][o] = acc;
    }
    __syncthreads();

    // y_const[b][c] = sum_o Wo[c,o] * v[b,o] + bo[c]
    int b = tid / CQ_;
    int c = tid % CQ_;
    float acc = bo[c];
    #pragma unroll
    for (int o = 0; o < INNER_; ++o)
        acc += Wo[c * INNER_ + o] * s_v[b][o];
    g_const[tid] = acc;
}

// Streaming broadcast fill: one float4 store per thread, exact mapping.
// Every 16B store lies entirely inside one slab (slabs are 1M-float aligned),
// so the constant index is i4 >> 18. The g_const load is an L1-hit broadcast.
__global__ void __launch_bounds__(256) fill_kernel(float4* __restrict__ out) {
    unsigned int i4 = blockIdx.x * 256u + threadIdx.x;   // < 2^25, fits u32
    float v = g_const[i4 >> 18];
    out[i4] = make_float4(v, v, v, v);
}

extern "C" void kernel_launch(void* const* d_in, const int* in_sizes, int n_in,
                              void* d_out, int out_size) {
    // metadata order: x, context, Wq, Wk, Wv, Wo, bo
    const float* context = (const float*)d_in[1];
    const float* Wv      = (const float*)d_in[4];
    const float* Wo      = (const float*)d_in[5];
    const float* bo      = (const float*)d_in[6];

    compute_consts_kernel<<<1, NCONST_>>>(context, Wv, Wo, bo);

    // out_size = 134,217,728 floats = 33,554,432 float4
    int n4 = out_size / 4;
    int blocks = n4 / 256;               // 131072 blocks, exact coverage
    fill_kernel<<<blocks, 256>>>((float4*)d_out);
}

// round 2
// speedup vs baseline: 1.0008x; 1.0008x over previous
#include <cuda_runtime.h>

// ChunkedValueCrossAttn: softmax over a single context token == 1.0, so the
// output is y[b,c,h,w] = (Wo @ (Wv @ context[b]))[c] + bo[c], a constant per
// (b,c) broadcast over HxW. x/Wq/Wk are dead inputs.
//
// Shapes: B=2, C=64, H=W=1024, inner=32, ctx=16.
// out: [2, 64, 1024, 1024] f32 = 134,217,728 elements = 536.9 MB (write-only).

#define B_       2
#define CQ_      64
#define INNER_   32
#define CTX_     16
#define NCONST_  (B_ * CQ_)             // 128
#define TPB_     256
#define F4_PER_THREAD_ 8
#define F4_PER_BLOCK_  (TPB_ * F4_PER_THREAD_)   // 2048 float4 = 32KB per block

__device__ float g_const[NCONST_];

// One block, 128 threads: compute the 128 broadcast constants.
__global__ void compute_consts_kernel(const float* __restrict__ context,
                                      const float* __restrict__ Wv,
                                      const float* __restrict__ Wo,
                                      const float* __restrict__ bo) {
    __shared__ float s_v[B_][INNER_];   // v = context @ Wv^T  -> [B, inner]
    int tid = threadIdx.x;

    if (tid < B_ * INNER_) {
        int b = tid / INNER_;
        int o = tid % INNER_;
        float acc = 0.f;
        #pragma unroll
        for (int j = 0; j < CTX_; ++j)
            acc += Wv[o * CTX_ + j] * context[b * CTX_ + j];
        s_v[b][o] = acc;
    }
    __syncthreads();

    // y_const[b][c] = sum_o Wo[c,o] * v[b,o] + bo[c]
    int b = tid / CQ_;
    int c = tid % CQ_;
    float acc = bo[c];
    #pragma unroll
    for (int o = 0; o < INNER_; ++o)
        acc += Wo[c * INNER_ + o] * s_v[b][o];
    g_const[tid] = acc;
}

// Streaming broadcast fill, 8 float4 per thread, iteration stride = blockDim
// so each STG.128 wavefront covers a contiguous 512B. Each block's 2048-f4
// (32KB) range lies wholly inside one 2^18-f4 slab (2048 | 2^18), so the
// broadcast constant is a single per-block L1-hit load: slab = blockIdx >> 7.
__global__ void __launch_bounds__(TPB_) fill_kernel(float4* __restrict__ out) {
    unsigned int base = blockIdx.x * (unsigned)F4_PER_BLOCK_ + threadIdx.x;
    float v = g_const[blockIdx.x >> 7];
    float4 f = make_float4(v, v, v, v);
    #pragma unroll
    for (int k = 0; k < F4_PER_THREAD_; ++k)
        out[base + k * (unsigned)TPB_] = f;
}

extern "C" void kernel_launch(void* const* d_in, const int* in_sizes, int n_in,
                              void* d_out, int out_size) {
    // metadata order: x, context, Wq, Wk, Wv, Wo, bo
    const float* context = (const float*)d_in[1];
    const float* Wv      = (const float*)d_in[4];
    const float* Wo      = (const float*)d_in[5];
    const float* bo      = (const float*)d_in[6];

    compute_consts_kernel<<<1, NCONST_>>>(context, Wv, Wo, bo);

    // out_size = 134,217,728 floats = 33,554,432 float4
    int n4 = out_size / 4;
    int blocks = n4 / F4_PER_BLOCK_;     // 16384 blocks, exact coverage
    fill_kernel<<<blocks, TPB_>>>((float4*)d_out);
}

// round 3
// speedup vs baseline: 1.0420x; 1.0412x over previous
#include <cuda_runtime.h>

// ChunkedValueCrossAttn: softmax over a single context token == 1.0, so the
// output is y[b,c,h,w] = (Wo @ (Wv @ context[b]))[c] + bo[c], a constant per
// (b,c) broadcast over HxW. x/Wq/Wk are dead inputs.
//
// Shapes: B=2, C=64, H=W=1024, inner=32, ctx=16.
// out: [2, 64, 1024, 1024] f32 = 536.9 MB write-only -> HBM store-bound.
//
// Single fused kernel: each block covers a 32KB range inside exactly one
// (b,c) slab, so it needs ONE constant. Warp 0 recomputes it (~550 FMAs on
// L2-hot weights), broadcasts through shared, then all 256 threads stream
// 8 float4 stores each. This removes the separate const-kernel launch and
// the serialized graph-node gap (~5us of round-2's total).

#define B_       2
#define CQ_      64
#define INNER_   32
#define CTX_     16
#define TPB_     256
#define F4_PER_THREAD_ 8
#define F4_PER_BLOCK_  (TPB_ * F4_PER_THREAD_)   // 2048 float4 = 32KB

__global__ void __launch_bounds__(TPB_) fused_fill_kernel(
        float4* __restrict__ out,
        const float* __restrict__ context,
        const float* __restrict__ Wv,
        const float* __restrict__ Wo,
        const float* __restrict__ bo) {
    __shared__ float s_c;

    unsigned int slab = blockIdx.x >> 7;       // 128 blocks per slab
    unsigned int b = slab >> 6;                // batch index
    unsigned int c = slab & 63u;               // channel index

    if (threadIdx.x < 32) {
        int o = threadIdx.x;                   // inner index, one per lane
        // v_o = dot(Wv[o,:], context[b,:])
        float v = 0.f;
        #pragma unroll
        for (int j = 0; j < CTX_; ++j)
            v += Wv[o * CTX_ + j] * context[b * CTX_ + j];
        // partial of y = sum_o Wo[c,o] * v_o
        float p = Wo[c * INNER_ + o] * v;
        // warp reduction over 32 lanes
        #pragma unroll
        for (int off = 16; off > 0; off >>= 1)
            p += __shfl_xor_sync(0xFFFFFFFFu, p, off);
        if (o == 0) s_c = p + bo[c];
    }
    __syncthreads();

    float val = s_c;
    float4 f = make_float4(val, val, val, val);
    unsigned int base = blockIdx.x * (unsigned)F4_PER_BLOCK_ + threadIdx.x;
    #pragma unroll
    for (int k = 0; k < F4_PER_THREAD_; ++k)
        out[base + k * (unsigned)TPB_] = f;
}

extern "C" void kernel_launch(void* const* d_in, const int* in_sizes, int n_in,
                              void* d_out, int out_size) {
    // metadata order: x, context, Wq, Wk, Wv, Wo, bo
    const float* context = (const float*)d_in[1];
    const float* Wv      = (const float*)d_in[4];
    const float* Wo      = (const float*)d_in[5];
    const float* bo      = (const float*)d_in[6];

    // out_size = 134,217,728 floats = 33,554,432 float4 -> 16384 blocks exact
    int n4 = out_size / 4;
    int blocks = n4 / F4_PER_BLOCK_;
    fused_fill_kernel<<<blocks, TPB_>>>((float4*)d_out, context, Wv, Wo, bo);
}